// round 12
// baseline (speedup 1.0000x reference)
#include <cuda_runtime.h>
#include <cuda_bf16.h>
#include <math.h>

#define Bb 2
#define Nn 286
#define HH 150
#define TE 8            // edges per tile (one tile per WARP)
#define MAXE 82944      // >= B*N*(N+1)/2 = 82082
#define PART4 205       // blocks per conv layer (4 warps * 205 = 820 tile slots)

typedef unsigned long long ULL;

// ---------------- device scratch (no allocations allowed) ----------------
// NOTE: only reference these from device code (host binding of a __device__
// symbol silently reads the host shadow via ATS on GB300).
__device__ int   g_edge_count;
__device__ int   g_packed[MAXE];  // (b<<20)|(i<<10)|j
__device__ float g_dist[MAXE];
__device__ float g_f0[Bb*Nn*4];
__device__ float g_f1[Bb*Nn*8];
__device__ float g_f2[Bb*Nn*8];
__device__ float g_f3[Bb*Nn*8];
__device__ float g_K0[MAXE*32];
__device__ float g_K1[MAXE*64];
__device__ float g_K2[MAXE*64];

__device__ __forceinline__ float sp_act(float x) {
    float t = 5.0f * x;
    if (t > 15.0f) return x;
    return 0.2f * __logf(1.0f + __expf(t));
}

// ---- packed fp32x2 FMA helpers (bit-exact 2x FFMA) ----
__device__ __forceinline__ void ffma2(ULL &d, ULL a, ULL b) {
    asm("fma.rn.f32x2 %0, %1, %2, %0;" : "+l"(d) : "l"(a), "l"(b));
}
__device__ __forceinline__ ULL bcast2(float w) {
    ULL r; asm("mov.b64 %0, {%1, %1};" : "=l"(r) : "f"(w)); return r;
}
__device__ __forceinline__ float2 unpk(ULL a) {
    float lo, hi; asm("mov.b64 {%0, %1}, %2;" : "=f"(lo), "=f"(hi) : "l"(a));
    return make_float2(lo, hi);
}

// ---------------- init kernels ----------------
__global__ void zero_kernel() {
    int t = blockIdx.x * blockDim.x + threadIdx.x;
    if (t == 0) g_edge_count = 0;
    if (t < Bb*Nn*8) { g_f1[t] = 0.f; g_f2[t] = 0.f; g_f3[t] = 0.f; }
}
__global__ void embed_kernel(const int* __restrict__ Z, const float* __restrict__ emb) {
    int t = blockIdx.x * blockDim.x + threadIdx.x;
    if (t < Bb*Nn*4) {
        int n = t >> 2, c = t & 3;
        g_f0[t] = emb[Z[n]*4 + c];
    }
}

// ---------------- build compacted unordered-pair list ----------------
__global__ void build_edges(const float* __restrict__ xyz) {
    int t = blockIdx.x * blockDim.x + threadIdx.x;
    if (t >= Bb*Nn*Nn) return;
    int b = t / (Nn*Nn);
    int r = t % (Nn*Nn);
    int i = r / Nn, j = r % Nn;
    if (j < i) return;
    const float* pi = xyz + (b*Nn + i)*3;
    const float* pj = xyz + (b*Nn + j)*3;
    float dx = pi[0]-pj[0], dy = pi[1]-pj[1], dz = pi[2]-pj[2];
    float d = sqrtf(dx*dx + dy*dy + dz*dz + 1e-12f);
    if (d <= 3.0f) {
        int idx = atomicAdd(&g_edge_count, 1);
        g_packed[idx] = (b << 20) | (i << 10) | j;
        g_dist[idx]   = d;
    }
}

// ---- store one activated unit row (8 edges) ----
__device__ __forceinline__ void store_row(float* __restrict__ dst, int row,
                                          const ULL* acc) {
    const float S = 0.0816496580927726f;   // 1/sqrt(150)
    float4* dr = reinterpret_cast<float4*>(dst + row*TE);
    float2 a = unpk(acc[0]), b = unpk(acc[1]);
    float2 c = unpk(acc[2]), d = unpk(acc[3]);
    float4 o0, o1;
    o0.x = sp_act(a.x*S); o0.y = sp_act(a.y*S);
    o0.z = sp_act(b.x*S); o0.w = sp_act(b.y*S);
    o1.x = sp_act(c.x*S); o1.y = sp_act(c.y*S);
    o1.z = sp_act(d.x*S); o1.w = sp_act(d.y*S);
    dr[0] = o0; dr[1] = o1;
}

// ---- hidden 150x150, single warp, 5 units/lane (unit = q*32+lane) --------
__device__ __forceinline__ void hidden5(const float* __restrict__ src,
                                        float* __restrict__ dst,
                                        const float* __restrict__ W, int lane) {
    ULL acc[5][4];
    #pragma unroll
    for (int q = 0; q < 5; q++)
        #pragma unroll
        for (int p = 0; p < 4; p++) acc[q][p] = 0ULL;
    const int uc4 = (128 + lane < HH) ? (128 + lane) : (HH - 1);
    #pragma unroll 1
    for (int kk = 0; kk < HH; kk += 3) {
        float w[5][3];
        #pragma unroll
        for (int u = 0; u < 3; u++) {
            const float* row = W + (kk + u)*HH;
            w[0][u] = __ldg(row + lane);
            w[1][u] = __ldg(row + 32 + lane);
            w[2][u] = __ldg(row + 64 + lane);
            w[3][u] = __ldg(row + 96 + lane);
            w[4][u] = __ldg(row + uc4);
        }
        #pragma unroll
        for (int u = 0; u < 3; u++) {
            const ulonglong2* hr = reinterpret_cast<const ulonglong2*>(src + (kk + u)*TE);
            ulonglong2 p0 = hr[0], p1 = hr[1];
            #pragma unroll
            for (int q = 0; q < 5; q++) {
                ULL wd = bcast2(w[q][u]);
                ffma2(acc[q][0], p0.x, wd); ffma2(acc[q][1], p0.y, wd);
                ffma2(acc[q][2], p1.x, wd); ffma2(acc[q][3], p1.y, wd);
            }
        }
    }
    #pragma unroll
    for (int q = 0; q < 5; q++) {
        int u = q*32 + lane;
        if (u < HH) store_row(dst, u, acc[q]);
    }
}

// ---- output layer: 150 -> DIO, single warp, NO=DIO/32 outputs/lane -------
template<int DIO>
__device__ __forceinline__ void out5(const float* __restrict__ HA_,
                                     const float* __restrict__ wo,
                                     float* __restrict__ Kout, int lane) {
    constexpr int NO = DIO / 32;    // 1 (conv0) or 2
    ULL acc[NO][4];
    #pragma unroll
    for (int n = 0; n < NO; n++)
        #pragma unroll
        for (int p = 0; p < 4; p++) acc[n][p] = 0ULL;
    #pragma unroll 1
    for (int kk = 0; kk < HH; kk += 3) {
        float w[NO][3];
        #pragma unroll
        for (int u = 0; u < 3; u++)
            #pragma unroll
            for (int n = 0; n < NO; n++)
                w[n][u] = __ldg(wo + (kk + u)*DIO + n*32 + lane);
        #pragma unroll
        for (int u = 0; u < 3; u++) {
            const ulonglong2* hr = reinterpret_cast<const ulonglong2*>(HA_ + (kk + u)*TE);
            ulonglong2 p0 = hr[0], p1 = hr[1];
            #pragma unroll
            for (int n = 0; n < NO; n++) {
                ULL wd = bcast2(w[n][u]);
                ffma2(acc[n][0], p0.x, wd); ffma2(acc[n][1], p0.y, wd);
                ffma2(acc[n][2], p1.x, wd); ffma2(acc[n][3], p1.y, wd);
            }
        }
    }
    #pragma unroll
    for (int n = 0; n < NO; n++) {
        int o = n*32 + lane;
        #pragma unroll
        for (int q = 0; q < 4; q++) {
            float2 v = unpk(acc[n][q]);
            Kout[(2*q    )*DIO + o] = v.x;
            Kout[(2*q + 1)*DIO + o] = v.y;
        }
    }
}

// ---------------- radial MLP: one tile per WARP, barrier-free --------------
__global__ __launch_bounds__(128)
void radial_kernel(const float* __restrict__ c0w1, const float* __restrict__ c0w2,
                   const float* __restrict__ c0w3, const float* __restrict__ c0wo,
                   const float* __restrict__ c1w1, const float* __restrict__ c1w2,
                   const float* __restrict__ c1w3, const float* __restrict__ c1wo,
                   const float* __restrict__ c2w1, const float* __restrict__ c2w2,
                   const float* __restrict__ c2w3, const float* __restrict__ c2wo) {
    __shared__ __align__(16) float HA[4][HH*TE + 8];
    __shared__ __align__(16) float HB[4][HH*TE + 8];
    __shared__ float SB[4][24];

    const int tid  = threadIdx.x;
    const int wid  = tid >> 5;
    const int lane = tid & 31;
    const int cnt = g_edge_count;
    const int ntiles = (cnt + TE - 1) / TE;
    const int layer = blockIdx.x / PART4;
    const int t0 = (blockIdx.x % PART4) * 4 + wid;
    const float INV_SQRT3 = 0.5773502691896258f;
    const float PI_2 = 1.5707963267948966f;

    const float *w1, *w2, *w3, *wo;
    if (layer == 0)      { w1 = c0w1; w2 = c0w2; w3 = c0w3; wo = c0wo; }
    else if (layer == 1) { w1 = c1w1; w2 = c1w2; w3 = c1w3; wo = c1wo; }
    else                 { w1 = c2w1; w2 = c2w2; w3 = c2w3; wo = c2wo; }

    float* ha = HA[wid];
    float* hb = HB[wid];
    float* sb = SB[wid];

    for (int tile = t0; tile < ntiles; tile += PART4*4) {
        // stage basis (lanes 0..7)
        if (lane < TE) {
            int idx = tile*TE + lane;
            float d = (idx < cnt) ? g_dist[idx] : 1e9f;
            float x0 = d * (1.0f/1.5f);
            float x1 = x0 - 1.0f;
            float x2 = x0 - 2.0f;
            float c0 = cosf(PI_2*x0), c1 = cosf(PI_2*x1), c2 = cosf(PI_2*x2);
            sb[lane]      = (fabsf(x0) < 1.f) ? c0*c0 : 0.f;
            sb[8 + lane]  = (fabsf(x1) < 1.f) ? c1*c1 : 0.f;
            sb[16 + lane] = (fabsf(x2) < 1.f) ? c2*c2 : 0.f;
        }
        __syncwarp();
        float s0[TE], s1[TE], s2[TE];
        #pragma unroll
        for (int e = 0; e < TE; e++) {
            s0[e] = sb[e]; s1[e] = sb[8 + e]; s2[e] = sb[16 + e];
        }

        // layer 1: basis(3) -> 150
        #pragma unroll
        for (int q = 0; q < 5; q++) {
            int u  = q*32 + lane;
            int uc = (u < HH) ? u : (HH - 1);
            float wa = w1[uc]        * INV_SQRT3;
            float wb = w1[HH + uc]   * INV_SQRT3;
            float wc = w1[2*HH + uc] * INV_SQRT3;
            if (u < HH) {
                float4 o0, o1;
                o0.x = sp_act(fmaf(s0[0], wa, fmaf(s1[0], wb, s2[0]*wc)));
                o0.y = sp_act(fmaf(s0[1], wa, fmaf(s1[1], wb, s2[1]*wc)));
                o0.z = sp_act(fmaf(s0[2], wa, fmaf(s1[2], wb, s2[2]*wc)));
                o0.w = sp_act(fmaf(s0[3], wa, fmaf(s1[3], wb, s2[3]*wc)));
                o1.x = sp_act(fmaf(s0[4], wa, fmaf(s1[4], wb, s2[4]*wc)));
                o1.y = sp_act(fmaf(s0[5], wa, fmaf(s1[5], wb, s2[5]*wc)));
                o1.z = sp_act(fmaf(s0[6], wa, fmaf(s1[6], wb, s2[6]*wc)));
                o1.w = sp_act(fmaf(s0[7], wa, fmaf(s1[7], wb, s2[7]*wc)));
                float4* dr = reinterpret_cast<float4*>(ha + u*TE);
                dr[0] = o0; dr[1] = o1;
            }
        }
        __syncwarp();
        hidden5(ha, hb, w2, lane);
        __syncwarp();
        hidden5(hb, ha, w3, lane);
        __syncwarp();

        if (layer == 0)      out5<32>(ha, wo, g_K0 + tile*TE*32, lane);
        else if (layer == 1) out5<64>(ha, wo, g_K1 + tile*TE*64, lane);
        else                 out5<64>(ha, wo, g_K2 + tile*TE*64, lane);
        __syncwarp();
    }
}

// ---------------- scatter: out[b,i] += K(e) @ f[b,j] (both directions) -----
template<int LAYER>
__global__ void scatter_kernel() {
    constexpr int DIN  = (LAYER == 0) ? 4 : 8;
    constexpr int DOUT = 8;
    const float* __restrict__ K   = (LAYER == 0) ? g_K0 : (LAYER == 1 ? g_K1 : g_K2);
    const float* __restrict__ fin = (LAYER == 0) ? g_f0 : (LAYER == 1 ? g_f1 : g_f2);
    float*       __restrict__ fout= (LAYER == 0) ? g_f1 : (LAYER == 1 ? g_f2 : g_f3);

    const int cnt = g_edge_count;
    const int total = cnt * DOUT;
    const float scale = rsqrtf(150.0f * (float)DIN);
    for (int t = blockIdx.x*blockDim.x + threadIdx.x; t < total;
         t += gridDim.x*blockDim.x) {
        int e = t / DOUT, a = t % DOUT;
        int p = g_packed[e];
        int b = p >> 20, i = (p >> 10) & 1023, j = p & 1023;
        const float* krow = K + e*(DIN*DOUT) + a*DIN;
        const float* fj = fin + (b*Nn + j)*DIN;
        const float* fi = fin + (b*Nn + i)*DIN;
        float s1 = 0.f, s2 = 0.f;
        #pragma unroll
        for (int ji = 0; ji < DIN; ji++) {
            float w = krow[ji];
            s1 = fmaf(w, fj[ji], s1);
            s2 = fmaf(w, fi[ji], s2);
        }
        atomicAdd(&fout[(b*Nn + i)*DOUT + a], s1 * scale);
        if (i != j) atomicAdd(&fout[(b*Nn + j)*DOUT + a], s2 * scale);
    }
}

// ---------------- epilogue: lp-pool, linear, batchnorm, leaky relu ----------
__global__ void final_kernel(const float* __restrict__ lin_w, const float* __restrict__ lin_b,
                             const float* __restrict__ bn_g,  const float* __restrict__ bn_b,
                             float* __restrict__ out) {
    __shared__ float pooled[2][24];
    __shared__ float yv[2][24];
    int t = threadIdx.x;
    if (t < 48) {
        int b = t / 24, c = t % 24;
        const float* src; int cc;
        if      (c < 8)  { src = g_f1; cc = c;      }
        else if (c < 16) { src = g_f2; cc = c - 8;  }
        else             { src = g_f3; cc = c - 16; }
        float s = 0.f;
        for (int n = 0; n < Nn; n++) {
            float v = src[(b*Nn + n)*8 + cc];
            s = fmaf(v, v, s);
        }
        pooled[b][c] = sqrtf(s + 1e-12f);
    }
    __syncthreads();
    if (t < 48) {
        int b = t / 24, o = t % 24;
        float s = lin_b[o];
        for (int c = 0; c < 24; c++) s = fmaf(pooled[b][c], lin_w[o*24 + c], s);
        yv[b][o] = s;
    }
    __syncthreads();
    if (t < 24) {
        float y0 = yv[0][t], y1 = yv[1][t];
        float m   = 0.5f * (y0 + y1);
        float d0  = y0 - m, d1 = y1 - m;
        float var = 0.5f * (d0*d0 + d1*d1);
        float inv = 1.0f / sqrtf(var + 1e-5f);
        #pragma unroll
        for (int b = 0; b < 2; b++) {
            float v = (yv[b][t] - m) * inv * bn_g[t] + bn_b[t];
            out[b*24 + t] = (v > 0.f) ? v : 0.2f * v;
        }
    }
}

// ---------------- launch (radial is 4th launch for ncu) --------------------
extern "C" void kernel_launch(void* const* d_in, const int* in_sizes, int n_in,
                              void* d_out, int out_size) {
    const float* xyz   = (const float*)d_in[0];
    const int*   Z     = (const int*)  d_in[1];
    const float* emb   = (const float*)d_in[2];
    const float* c0w1  = (const float*)d_in[3];
    const float* c0w2  = (const float*)d_in[4];
    const float* c0w3  = (const float*)d_in[5];
    const float* c0wo  = (const float*)d_in[6];
    const float* c1w1  = (const float*)d_in[7];
    const float* c1w2  = (const float*)d_in[8];
    const float* c1w3  = (const float*)d_in[9];
    const float* c1wo  = (const float*)d_in[10];
    const float* c2w1  = (const float*)d_in[11];
    const float* c2w2  = (const float*)d_in[12];
    const float* c2w3  = (const float*)d_in[13];
    const float* c2wo  = (const float*)d_in[14];
    const float* lin_w = (const float*)d_in[15];
    const float* lin_b = (const float*)d_in[16];
    const float* bn_g  = (const float*)d_in[17];
    const float* bn_b  = (const float*)d_in[18];
    float* out = (float*)d_out;

    zero_kernel<<<18, 256>>>();
    embed_kernel<<<(Bb*Nn*4 + 255)/256, 256>>>(Z, emb);
    build_edges<<<(Bb*Nn*Nn + 255)/256, 256>>>(xyz);
    radial_kernel<<<3*PART4, 128>>>(c0w1, c0w2, c0w3, c0wo,
                                    c1w1, c1w2, c1w3, c1wo,
                                    c2w1, c2w2, c2w3, c2wo);
    scatter_kernel<0><<<296, 256>>>();
    scatter_kernel<1><<<296, 256>>>();
    scatter_kernel<2><<<296, 256>>>();
    final_kernel<<<1, 64>>>(lin_w, lin_b, bn_g, bn_b, out);
}

// round 13
// speedup vs baseline: 1.1580x; 1.1580x over previous
#include <cuda_runtime.h>
#include <cuda_bf16.h>
#include <math.h>

#define Bb 2
#define Nn 286
#define HH 150
#define TE 4            // edges per tile (one tile per WARP)
#define MAXE 82944      // >= B*N*(N+1)/2 = 82082
#define PART 420        // blocks per conv layer (4 warps * 420 = 1680 warp-tile slots)
#define CH 38           // k-chunks of 4 (150 -> 152 padded)
#define UP 160          // padded unit count (5 groups of 32)

typedef unsigned long long ULL;

// ---------------- device scratch (no allocations allowed) ----------------
// NOTE: only reference these from device code (host binding of a __device__
// symbol silently reads the host shadow via ATS on GB300).
__device__ int   g_edge_count;
__device__ int   g_packed[MAXE];  // (b<<20)|(i<<10)|j
__device__ float g_dist[MAXE];
__device__ float g_f0[Bb*Nn*4];
__device__ float g_f1[Bb*Nn*8];
__device__ float g_f2[Bb*Nn*8];
__device__ float g_f3[Bb*Nn*8];
__device__ float g_K0[MAXE*32];
__device__ float g_K1[MAXE*64];
__device__ float g_K2[MAXE*64];
// k-interleaved repacked weights: Wh[conv*2+L][c*UP*4 + u*4 + (k%4)]
__device__ float g_Wh[6][CH*UP*4];
__device__ float g_Wo0[CH*32*4];
__device__ float g_Wo1[CH*64*4];
__device__ float g_Wo2[CH*64*4];

__device__ __forceinline__ float sp_act(float x) {
    float t = 5.0f * x;
    if (t > 15.0f) return x;
    return 0.2f * __logf(1.0f + __expf(t));
}

// ---- packed fp32x2 FMA helpers (bit-exact 2x FFMA) ----
__device__ __forceinline__ void ffma2(ULL &d, ULL a, ULL b) {
    asm("fma.rn.f32x2 %0, %1, %2, %0;" : "+l"(d) : "l"(a), "l"(b));
}
__device__ __forceinline__ ULL bcast2(float w) {
    ULL r; asm("mov.b64 %0, {%1, %1};" : "=l"(r) : "f"(w)); return r;
}
__device__ __forceinline__ float2 unpk(ULL a) {
    float lo, hi; asm("mov.b64 {%0, %1}, %2;" : "=f"(lo), "=f"(hi) : "l"(a));
    return make_float2(lo, hi);
}

// ---------------- init kernels ----------------
__global__ void zero_kernel() {
    int t = blockIdx.x * blockDim.x + threadIdx.x;
    if (t == 0) g_edge_count = 0;
    if (t < Bb*Nn*8) { g_f1[t] = 0.f; g_f2[t] = 0.f; g_f3[t] = 0.f; }
}
__global__ void embed_kernel(const int* __restrict__ Z, const float* __restrict__ emb) {
    int t = blockIdx.x * blockDim.x + threadIdx.x;
    if (t < Bb*Nn*4) {
        int n = t >> 2, c = t & 3;
        g_f0[t] = emb[Z[n]*4 + c];
    }
}

// ---------------- build compacted unordered-pair list ----------------
__global__ void build_edges(const float* __restrict__ xyz) {
    int t = blockIdx.x * blockDim.x + threadIdx.x;
    if (t >= Bb*Nn*Nn) return;
    int b = t / (Nn*Nn);
    int r = t % (Nn*Nn);
    int i = r / Nn, j = r % Nn;
    if (j < i) return;
    const float* pi = xyz + (b*Nn + i)*3;
    const float* pj = xyz + (b*Nn + j)*3;
    float dx = pi[0]-pj[0], dy = pi[1]-pj[1], dz = pi[2]-pj[2];
    float d = sqrtf(dx*dx + dy*dy + dz*dz + 1e-12f);
    if (d <= 3.0f) {
        int idx = atomicAdd(&g_edge_count, 1);
        g_packed[idx] = (b << 20) | (i << 10) | j;
        g_dist[idx]   = d;
    }
}

// ---------------- weight repack: k-interleaved float4 groups ---------------
__global__ void repack_kernel(const float* __restrict__ c0w2, const float* __restrict__ c0w3,
                              const float* __restrict__ c1w2, const float* __restrict__ c1w3,
                              const float* __restrict__ c2w2, const float* __restrict__ c2w3,
                              const float* __restrict__ c0wo, const float* __restrict__ c1wo,
                              const float* __restrict__ c2wo) {
    const int HSZ = CH*UP*4;
    const int O32 = CH*32*4, O64 = CH*64*4;
    int t = blockIdx.x * blockDim.x + threadIdx.x;
    if (t < 6*HSZ) {
        int m = t / HSZ, e = t % HSZ;
        int c = e / (UP*4), r = e % (UP*4), u = r >> 2, ck = r & 3;
        int k = c*4 + ck;
        const float* W = (m == 0) ? c0w2 : (m == 1) ? c0w3 :
                         (m == 2) ? c1w2 : (m == 3) ? c1w3 :
                         (m == 4) ? c2w2 : c2w3;
        g_Wh[m][e] = (u < HH && k < HH) ? W[k*HH + u] : 0.f;
        return;
    }
    t -= 6*HSZ;
    if (t < O32) {
        int c = t / (32*4), r = t % (32*4), u = r >> 2, ck = r & 3;
        int k = c*4 + ck;
        g_Wo0[t] = (k < HH) ? c0wo[k*32 + u] : 0.f;
        return;
    }
    t -= O32;
    if (t < O64) {
        int c = t / (64*4), r = t % (64*4), u = r >> 2, ck = r & 3;
        int k = c*4 + ck;
        g_Wo1[t] = (k < HH) ? c1wo[k*64 + u] : 0.f;
        return;
    }
    t -= O64;
    if (t < O64) {
        int c = t / (64*4), r = t % (64*4), u = r >> 2, ck = r & 3;
        int k = c*4 + ck;
        g_Wo2[t] = (k < HH) ? c2wo[k*64 + u] : 0.f;
    }
}

// ---- store one activated unit row (4 edges) ----
__device__ __forceinline__ void store_row4(float* __restrict__ dst, int row,
                                           const ULL* acc) {
    const float S = 0.0816496580927726f;   // 1/sqrt(150)
    float2 a = unpk(acc[0]), b = unpk(acc[1]);
    float4 o;
    o.x = sp_act(a.x*S); o.y = sp_act(a.y*S);
    o.z = sp_act(b.x*S); o.w = sp_act(b.y*S);
    *reinterpret_cast<float4*>(dst + row*TE) = o;
}

// ---- hidden 150x150, single warp, 5 units/lane, repacked float4 weights ---
__device__ __forceinline__ void hidden4(const float* __restrict__ src,
                                        float* __restrict__ dst,
                                        const float* __restrict__ Wp, int lane) {
    ULL acc[5][2];
    #pragma unroll
    for (int q = 0; q < 5; q++) { acc[q][0] = 0ULL; acc[q][1] = 0ULL; }
    #pragma unroll 1
    for (int c = 0; c < CH; c++) {
        float4 w[5];
        #pragma unroll
        for (int q = 0; q < 5; q++)
            w[q] = *reinterpret_cast<const float4*>(Wp + (c*UP + q*32 + lane)*4);
        #pragma unroll
        for (int ck = 0; ck < 4; ck++) {
            ulonglong2 p = *reinterpret_cast<const ulonglong2*>(src + (c*4 + ck)*TE);
            float wv0 = (ck==0)?w[0].x:(ck==1)?w[0].y:(ck==2)?w[0].z:w[0].w;
            float wv1 = (ck==0)?w[1].x:(ck==1)?w[1].y:(ck==2)?w[1].z:w[1].w;
            float wv2 = (ck==0)?w[2].x:(ck==1)?w[2].y:(ck==2)?w[2].z:w[2].w;
            float wv3 = (ck==0)?w[3].x:(ck==1)?w[3].y:(ck==2)?w[3].z:w[3].w;
            float wv4 = (ck==0)?w[4].x:(ck==1)?w[4].y:(ck==2)?w[4].z:w[4].w;
            ULL d0 = bcast2(wv0), d1 = bcast2(wv1), d2 = bcast2(wv2);
            ULL d3 = bcast2(wv3), d4 = bcast2(wv4);
            ffma2(acc[0][0], p.x, d0); ffma2(acc[0][1], p.y, d0);
            ffma2(acc[1][0], p.x, d1); ffma2(acc[1][1], p.y, d1);
            ffma2(acc[2][0], p.x, d2); ffma2(acc[2][1], p.y, d2);
            ffma2(acc[3][0], p.x, d3); ffma2(acc[3][1], p.y, d3);
            ffma2(acc[4][0], p.x, d4); ffma2(acc[4][1], p.y, d4);
        }
    }
    #pragma unroll
    for (int q = 0; q < 5; q++) {
        int u = q*32 + lane;
        if (u < HH) store_row4(dst, u, acc[q]);
    }
}

// ---- output layer: 150 -> DIO, single warp, repacked weights --------------
template<int DIO>
__device__ __forceinline__ void out4(const float* __restrict__ src,
                                     const float* __restrict__ Wop,
                                     float* __restrict__ Kout, int lane) {
    constexpr int NO = DIO / 32;    // 1 (conv0) or 2
    ULL acc[NO][2];
    #pragma unroll
    for (int n = 0; n < NO; n++) { acc[n][0] = 0ULL; acc[n][1] = 0ULL; }
    #pragma unroll 1
    for (int c = 0; c < CH; c++) {
        float4 w[NO];
        #pragma unroll
        for (int n = 0; n < NO; n++)
            w[n] = *reinterpret_cast<const float4*>(Wop + (c*DIO + n*32 + lane)*4);
        #pragma unroll
        for (int ck = 0; ck < 4; ck++) {
            ulonglong2 p = *reinterpret_cast<const ulonglong2*>(src + (c*4 + ck)*TE);
            #pragma unroll
            for (int n = 0; n < NO; n++) {
                float wv = (ck==0)?w[n].x:(ck==1)?w[n].y:(ck==2)?w[n].z:w[n].w;
                ULL wd = bcast2(wv);
                ffma2(acc[n][0], p.x, wd); ffma2(acc[n][1], p.y, wd);
            }
        }
    }
    #pragma unroll
    for (int n = 0; n < NO; n++) {
        int o = n*32 + lane;
        float2 v0 = unpk(acc[n][0]), v1 = unpk(acc[n][1]);
        Kout[0*DIO + o] = v0.x;
        Kout[1*DIO + o] = v0.y;
        Kout[2*DIO + o] = v1.x;
        Kout[3*DIO + o] = v1.y;
    }
}

// ---------------- radial MLP: one 4-edge tile per WARP, barrier-free -------
__global__ __launch_bounds__(128)
void radial_kernel(const float* __restrict__ c0w1, const float* __restrict__ c1w1,
                   const float* __restrict__ c2w1) {
    __shared__ __align__(16) float HA[4][(HH+2)*TE];
    __shared__ __align__(16) float HB[4][(HH+2)*TE];
    __shared__ float SB[4][12];

    const int tid  = threadIdx.x;
    const int wid  = tid >> 5;
    const int lane = tid & 31;
    const int cnt = g_edge_count;
    const int ntiles = (cnt + TE - 1) / TE;
    const int layer = blockIdx.x / PART;
    const int t0 = (blockIdx.x % PART) * 4 + wid;
    const float INV_SQRT3 = 0.5773502691896258f;
    const float PI_2 = 1.5707963267948966f;

    const float* w1 = (layer == 0) ? c0w1 : (layer == 1) ? c1w1 : c2w1;
    const float* Wh2 = g_Wh[layer*2];
    const float* Wh3 = g_Wh[layer*2 + 1];

    float* ha = HA[wid];
    float* hb = HB[wid];
    float* sb = SB[wid];

    // zero the k-padding rows (150,151) once — weights there are 0 but
    // activations must be finite for FFMA2
    if (lane < 2*TE) { ha[HH*TE + lane] = 0.f; hb[HH*TE + lane] = 0.f; }

    for (int tile = t0; tile < ntiles; tile += PART*4) {
        // stage basis (lanes 0..3)
        if (lane < TE) {
            int idx = tile*TE + lane;
            float d = (idx < cnt) ? g_dist[idx] : 1e9f;
            float x0 = d * (1.0f/1.5f);
            float x1 = x0 - 1.0f;
            float x2 = x0 - 2.0f;
            float c0 = cosf(PI_2*x0), c1 = cosf(PI_2*x1), c2 = cosf(PI_2*x2);
            sb[lane]     = (fabsf(x0) < 1.f) ? c0*c0 : 0.f;
            sb[4 + lane] = (fabsf(x1) < 1.f) ? c1*c1 : 0.f;
            sb[8 + lane] = (fabsf(x2) < 1.f) ? c2*c2 : 0.f;
        }
        __syncwarp();
        float s0[TE], s1[TE], s2[TE];
        #pragma unroll
        for (int e = 0; e < TE; e++) {
            s0[e] = sb[e]; s1[e] = sb[4 + e]; s2[e] = sb[8 + e];
        }

        // layer 1: basis(3) -> 150
        #pragma unroll
        for (int q = 0; q < 5; q++) {
            int u = q*32 + lane;
            if (u < HH) {
                float wa = w1[u]        * INV_SQRT3;
                float wb = w1[HH + u]   * INV_SQRT3;
                float wc = w1[2*HH + u] * INV_SQRT3;
                float4 o;
                o.x = sp_act(fmaf(s0[0], wa, fmaf(s1[0], wb, s2[0]*wc)));
                o.y = sp_act(fmaf(s0[1], wa, fmaf(s1[1], wb, s2[1]*wc)));
                o.z = sp_act(fmaf(s0[2], wa, fmaf(s1[2], wb, s2[2]*wc)));
                o.w = sp_act(fmaf(s0[3], wa, fmaf(s1[3], wb, s2[3]*wc)));
                *reinterpret_cast<float4*>(ha + u*TE) = o;
            }
        }
        __syncwarp();
        hidden4(ha, hb, Wh2, lane);
        __syncwarp();
        hidden4(hb, ha, Wh3, lane);
        __syncwarp();

        if (layer == 0)      out4<32>(ha, g_Wo0, g_K0 + tile*TE*32, lane);
        else if (layer == 1) out4<64>(ha, g_Wo1, g_K1 + tile*TE*64, lane);
        else                 out4<64>(ha, g_Wo2, g_K2 + tile*TE*64, lane);
        __syncwarp();
    }
}

// ---------------- scatter: out[b,i] += K(e) @ f[b,j] (both directions) -----
template<int LAYER>
__global__ void scatter_kernel() {
    constexpr int DIN  = (LAYER == 0) ? 4 : 8;
    constexpr int DOUT = 8;
    const float* __restrict__ K   = (LAYER == 0) ? g_K0 : (LAYER == 1 ? g_K1 : g_K2);
    const float* __restrict__ fin = (LAYER == 0) ? g_f0 : (LAYER == 1 ? g_f1 : g_f2);
    float*       __restrict__ fout= (LAYER == 0) ? g_f1 : (LAYER == 1 ? g_f2 : g_f3);

    const int cnt = g_edge_count;
    const int total = cnt * DOUT;
    const float scale = rsqrtf(150.0f * (float)DIN);
    for (int t = blockIdx.x*blockDim.x + threadIdx.x; t < total;
         t += gridDim.x*blockDim.x) {
        int e = t / DOUT, a = t % DOUT;
        int p = g_packed[e];
        int b = p >> 20, i = (p >> 10) & 1023, j = p & 1023;
        const float* krow = K + e*(DIN*DOUT) + a*DIN;
        const float* fj = fin + (b*Nn + j)*DIN;
        const float* fi = fin + (b*Nn + i)*DIN;
        float s1 = 0.f, s2 = 0.f;
        #pragma unroll
        for (int ji = 0; ji < DIN; ji++) {
            float w = krow[ji];
            s1 = fmaf(w, fj[ji], s1);
            s2 = fmaf(w, fi[ji], s2);
        }
        atomicAdd(&fout[(b*Nn + i)*DOUT + a], s1 * scale);
        if (i != j) atomicAdd(&fout[(b*Nn + j)*DOUT + a], s2 * scale);
    }
}

// ---------------- epilogue: lp-pool, linear, batchnorm, leaky relu ----------
__global__ void final_kernel(const float* __restrict__ lin_w, const float* __restrict__ lin_b,
                             const float* __restrict__ bn_g,  const float* __restrict__ bn_b,
                             float* __restrict__ out) {
    __shared__ float pooled[2][24];
    __shared__ float yv[2][24];
    int t = threadIdx.x;
    if (t < 48) {
        int b = t / 24, c = t % 24;
        const float* src; int cc;
        if      (c < 8)  { src = g_f1; cc = c;      }
        else if (c < 16) { src = g_f2; cc = c - 8;  }
        else             { src = g_f3; cc = c - 16; }
        float s = 0.f;
        for (int n = 0; n < Nn; n++) {
            float v = src[(b*Nn + n)*8 + cc];
            s = fmaf(v, v, s);
        }
        pooled[b][c] = sqrtf(s + 1e-12f);
    }
    __syncthreads();
    if (t < 48) {
        int b = t / 24, o = t % 24;
        float s = lin_b[o];
        for (int c = 0; c < 24; c++) s = fmaf(pooled[b][c], lin_w[o*24 + c], s);
        yv[b][o] = s;
    }
    __syncthreads();
    if (t < 24) {
        float y0 = yv[0][t], y1 = yv[1][t];
        float m   = 0.5f * (y0 + y1);
        float d0  = y0 - m, d1 = y1 - m;
        float var = 0.5f * (d0*d0 + d1*d1);
        float inv = 1.0f / sqrtf(var + 1e-5f);
        #pragma unroll
        for (int b = 0; b < 2; b++) {
            float v = (yv[b][t] - m) * inv * bn_g[t] + bn_b[t];
            out[b*24 + t] = (v > 0.f) ? v : 0.2f * v;
        }
    }
}

// ---------------- launch ----------------
extern "C" void kernel_launch(void* const* d_in, const int* in_sizes, int n_in,
                              void* d_out, int out_size) {
    const float* xyz   = (const float*)d_in[0];
    const int*   Z     = (const int*)  d_in[1];
    const float* emb   = (const float*)d_in[2];
    const float* c0w1  = (const float*)d_in[3];
    const float* c0w2  = (const float*)d_in[4];
    const float* c0w3  = (const float*)d_in[5];
    const float* c0wo  = (const float*)d_in[6];
    const float* c1w1  = (const float*)d_in[7];
    const float* c1w2  = (const float*)d_in[8];
    const float* c1w3  = (const float*)d_in[9];
    const float* c1wo  = (const float*)d_in[10];
    const float* c2w1  = (const float*)d_in[11];
    const float* c2w2  = (const float*)d_in[12];
    const float* c2w3  = (const float*)d_in[13];
    const float* c2wo  = (const float*)d_in[14];
    const float* lin_w = (const float*)d_in[15];
    const float* lin_b = (const float*)d_in[16];
    const float* bn_g  = (const float*)d_in[17];
    const float* bn_b  = (const float*)d_in[18];
    float* out = (float*)d_out;

    zero_kernel<<<18, 256>>>();
    embed_kernel<<<(Bb*Nn*4 + 255)/256, 256>>>(Z, emb);
    build_edges<<<(Bb*Nn*Nn + 255)/256, 256>>>(xyz);
    repack_kernel<<<666, 256>>>(c0w2, c0w3, c1w2, c1w3, c2w2, c2w3,
                                c0wo, c1wo, c2wo);
    radial_kernel<<<3*PART, 128>>>(c0w1, c1w1, c2w1);
    scatter_kernel<0><<<296, 256>>>();
    scatter_kernel<1><<<296, 256>>>();
    scatter_kernel<2><<<296, 256>>>();
    final_kernel<<<1, 64>>>(lin_w, lin_b, bn_g, bn_b, out);
}

// round 15
// speedup vs baseline: 1.1810x; 1.0199x over previous
#include <cuda_runtime.h>
#include <cuda_bf16.h>
#include <math.h>

#define Bb 2
#define Nn 286
#define HH 150
#define TE 4            // edges per tile (one tile per WARP)
#define MAXE 82944      // >= B*N*(N+1)/2 = 82082
#define PART 420        // blocks per conv layer (4 warps * 420 = 1680 warp-tile slots)
#define CH 38           // k-chunks of 4 (150 -> 152 padded)
#define UP 160          // padded unit count (5 groups of 32)

typedef unsigned long long ULL;

// ---------------- device scratch (no allocations allowed) ----------------
// NOTE: only reference these from device code (host binding of a __device__
// symbol silently reads the host shadow via ATS on GB300).
__device__ int   g_edge_count;
__device__ int   g_done;
__device__ int   g_packed[MAXE];  // (b<<20)|(i<<10)|j
__device__ float g_dist[MAXE];
__device__ float g_f0[Bb*Nn*4];
__device__ float g_f1[Bb*Nn*8];
__device__ float g_f2[Bb*Nn*8];
__device__ float g_f3[Bb*Nn*8];
__device__ float g_K0[MAXE*32];
__device__ float g_K1[MAXE*64];
__device__ float g_K2[MAXE*64];
// k-interleaved repacked weights: Wh[conv*2+L][c*UP*4 + u*4 + (k%4)]
__device__ float g_Wh[6][CH*UP*4];
__device__ float g_Wo0[CH*32*4];
__device__ float g_Wo1[CH*64*4];
__device__ float g_Wo2[CH*64*4];

__device__ __forceinline__ float sp_act(float x) {
    float t = 5.0f * x;
    if (t > 15.0f) return x;
    return 0.2f * __logf(1.0f + __expf(t));
}

// ---- packed fp32x2 FMA helpers (bit-exact 2x FFMA) ----
__device__ __forceinline__ void ffma2(ULL &d, ULL a, ULL b) {
    asm("fma.rn.f32x2 %0, %1, %2, %0;" : "+l"(d) : "l"(a), "l"(b));
}
__device__ __forceinline__ ULL bcast2(float w) {
    ULL r; asm("mov.b64 %0, {%1, %1};" : "=l"(r) : "f"(w)); return r;
}
__device__ __forceinline__ float2 unpk(ULL a) {
    float lo, hi; asm("mov.b64 {%0, %1}, %2;" : "=f"(lo), "=f"(hi) : "l"(a));
    return make_float2(lo, hi);
}

// ---------------- reset: counters only (must precede prep; no race) -------
__global__ void reset_kernel() {
    if (threadIdx.x == 0) { g_edge_count = 0; g_done = 0; }
}

// ---------------- unified prep: zero + embed + build + repack --------------
// blocks [0,18): zero accumulators + embed
// blocks [18,658): build edge list (163592 items)
// blocks [658,1324): weight repack (170240 items)
__global__ void prep_kernel(const int* __restrict__ Z, const float* __restrict__ emb,
                            const float* __restrict__ xyz,
                            const float* __restrict__ c0w2, const float* __restrict__ c0w3,
                            const float* __restrict__ c1w2, const float* __restrict__ c1w3,
                            const float* __restrict__ c2w2, const float* __restrict__ c2w3,
                            const float* __restrict__ c0wo, const float* __restrict__ c1wo,
                            const float* __restrict__ c2wo) {
    const int b = blockIdx.x;
    if (b < 18) {
        int t = b*256 + threadIdx.x;
        if (t < Bb*Nn*8) { g_f1[t] = 0.f; g_f2[t] = 0.f; g_f3[t] = 0.f; }
        if (t < Bb*Nn*4) {
            int n = t >> 2, c = t & 3;
            g_f0[t] = emb[Z[n]*4 + c];
        }
        return;
    }
    if (b < 658) {
        int t = (b - 18)*256 + threadIdx.x;
        if (t >= Bb*Nn*Nn) return;
        int bb = t / (Nn*Nn);
        int r = t % (Nn*Nn);
        int i = r / Nn, j = r % Nn;
        if (j < i) return;
        const float* pi = xyz + (bb*Nn + i)*3;
        const float* pj = xyz + (bb*Nn + j)*3;
        float dx = pi[0]-pj[0], dy = pi[1]-pj[1], dz = pi[2]-pj[2];
        float d = sqrtf(dx*dx + dy*dy + dz*dz + 1e-12f);
        if (d <= 3.0f) {
            int idx = atomicAdd(&g_edge_count, 1);
            g_packed[idx] = (bb << 20) | (i << 10) | j;
            g_dist[idx]   = d;
        }
        return;
    }
    {
        const int HSZ = CH*UP*4;
        const int O32 = CH*32*4, O64 = CH*64*4;
        int t = (b - 658)*256 + threadIdx.x;
        if (t < 6*HSZ) {
            int m = t / HSZ, e = t % HSZ;
            int c = e / (UP*4), r = e % (UP*4), u = r >> 2, ck = r & 3;
            int k = c*4 + ck;
            const float* W = (m == 0) ? c0w2 : (m == 1) ? c0w3 :
                             (m == 2) ? c1w2 : (m == 3) ? c1w3 :
                             (m == 4) ? c2w2 : c2w3;
            g_Wh[m][e] = (u < HH && k < HH) ? W[k*HH + u] : 0.f;
            return;
        }
        t -= 6*HSZ;
        if (t < O32) {
            int c = t / (32*4), r = t % (32*4), u = r >> 2, ck = r & 3;
            int k = c*4 + ck;
            g_Wo0[t] = (k < HH) ? c0wo[k*32 + u] : 0.f;
            return;
        }
        t -= O32;
        if (t < O64) {
            int c = t / (64*4), r = t % (64*4), u = r >> 2, ck = r & 3;
            int k = c*4 + ck;
            g_Wo1[t] = (k < HH) ? c1wo[k*64 + u] : 0.f;
            return;
        }
        t -= O64;
        if (t < O64) {
            int c = t / (64*4), r = t % (64*4), u = r >> 2, ck = r & 3;
            int k = c*4 + ck;
            g_Wo2[t] = (k < HH) ? c2wo[k*64 + u] : 0.f;
        }
    }
}

// ---- store one activated unit row (4 edges) ----
__device__ __forceinline__ void store_row4(float* __restrict__ dst, int row,
                                           const ULL* acc) {
    const float S = 0.0816496580927726f;   // 1/sqrt(150)
    float2 a = unpk(acc[0]), b = unpk(acc[1]);
    float4 o;
    o.x = sp_act(a.x*S); o.y = sp_act(a.y*S);
    o.z = sp_act(b.x*S); o.w = sp_act(b.y*S);
    *reinterpret_cast<float4*>(dst + row*TE) = o;
}

// ---- hidden 150x150, single warp, 5 units/lane, repacked float4 weights ---
__device__ __forceinline__ void hidden4(const float* __restrict__ src,
                                        float* __restrict__ dst,
                                        const float* __restrict__ Wp, int lane) {
    ULL acc[5][2];
    #pragma unroll
    for (int q = 0; q < 5; q++) { acc[q][0] = 0ULL; acc[q][1] = 0ULL; }
    #pragma unroll 1
    for (int c = 0; c < CH; c++) {
        float4 w[5];
        #pragma unroll
        for (int q = 0; q < 5; q++)
            w[q] = *reinterpret_cast<const float4*>(Wp + (c*UP + q*32 + lane)*4);
        #pragma unroll
        for (int ck = 0; ck < 4; ck++) {
            ulonglong2 p = *reinterpret_cast<const ulonglong2*>(src + (c*4 + ck)*TE);
            float wv0 = (ck==0)?w[0].x:(ck==1)?w[0].y:(ck==2)?w[0].z:w[0].w;
            float wv1 = (ck==0)?w[1].x:(ck==1)?w[1].y:(ck==2)?w[1].z:w[1].w;
            float wv2 = (ck==0)?w[2].x:(ck==1)?w[2].y:(ck==2)?w[2].z:w[2].w;
            float wv3 = (ck==0)?w[3].x:(ck==1)?w[3].y:(ck==2)?w[3].z:w[3].w;
            float wv4 = (ck==0)?w[4].x:(ck==1)?w[4].y:(ck==2)?w[4].z:w[4].w;
            ULL d0 = bcast2(wv0), d1 = bcast2(wv1), d2 = bcast2(wv2);
            ULL d3 = bcast2(wv3), d4 = bcast2(wv4);
            ffma2(acc[0][0], p.x, d0); ffma2(acc[0][1], p.y, d0);
            ffma2(acc[1][0], p.x, d1); ffma2(acc[1][1], p.y, d1);
            ffma2(acc[2][0], p.x, d2); ffma2(acc[2][1], p.y, d2);
            ffma2(acc[3][0], p.x, d3); ffma2(acc[3][1], p.y, d3);
            ffma2(acc[4][0], p.x, d4); ffma2(acc[4][1], p.y, d4);
        }
    }
    #pragma unroll
    for (int q = 0; q < 5; q++) {
        int u = q*32 + lane;
        if (u < HH) store_row4(dst, u, acc[q]);
    }
}

// ---- output layer: 150 -> DIO, single warp, repacked weights --------------
template<int DIO>
__device__ __forceinline__ void out4(const float* __restrict__ src,
                                     const float* __restrict__ Wop,
                                     float* __restrict__ Kout, int lane) {
    constexpr int NO = DIO / 32;    // 1 (conv0) or 2
    ULL acc[NO][2];
    #pragma unroll
    for (int n = 0; n < NO; n++) { acc[n][0] = 0ULL; acc[n][1] = 0ULL; }
    #pragma unroll 1
    for (int c = 0; c < CH; c++) {
        float4 w[NO];
        #pragma unroll
        for (int n = 0; n < NO; n++)
            w[n] = *reinterpret_cast<const float4*>(Wop + (c*DIO + n*32 + lane)*4);
        #pragma unroll
        for (int ck = 0; ck < 4; ck++) {
            ulonglong2 p = *reinterpret_cast<const ulonglong2*>(src + (c*4 + ck)*TE);
            #pragma unroll
            for (int n = 0; n < NO; n++) {
                float wv = (ck==0)?w[n].x:(ck==1)?w[n].y:(ck==2)?w[n].z:w[n].w;
                ULL wd = bcast2(wv);
                ffma2(acc[n][0], p.x, wd); ffma2(acc[n][1], p.y, wd);
            }
        }
    }
    #pragma unroll
    for (int n = 0; n < NO; n++) {
        int o = n*32 + lane;
        float2 v0 = unpk(acc[n][0]), v1 = unpk(acc[n][1]);
        Kout[0*DIO + o] = v0.x;
        Kout[1*DIO + o] = v0.y;
        Kout[2*DIO + o] = v1.x;
        Kout[3*DIO + o] = v1.y;
    }
}

// ---------------- radial MLP: one 4-edge tile per WARP, barrier-free -------
__global__ __launch_bounds__(128)
void radial_kernel(const float* __restrict__ c0w1, const float* __restrict__ c1w1,
                   const float* __restrict__ c2w1) {
    __shared__ __align__(16) float HA[4][(HH+2)*TE];
    __shared__ __align__(16) float HB[4][(HH+2)*TE];
    __shared__ float SB[4][12];

    const int tid  = threadIdx.x;
    const int wid  = tid >> 5;
    const int lane = tid & 31;
    const int cnt = g_edge_count;
    const int ntiles = (cnt + TE - 1) / TE;
    const int layer = blockIdx.x / PART;
    const int t0 = (blockIdx.x % PART) * 4 + wid;
    const float INV_SQRT3 = 0.5773502691896258f;
    const float PI_2 = 1.5707963267948966f;

    const float* w1 = (layer == 0) ? c0w1 : (layer == 1) ? c1w1 : c2w1;
    const float* Wh2 = g_Wh[layer*2];
    const float* Wh3 = g_Wh[layer*2 + 1];

    float* ha = HA[wid];
    float* hb = HB[wid];
    float* sb = SB[wid];

    // zero the k-padding rows (150,151)
    if (lane < 2*TE) { ha[HH*TE + lane] = 0.f; hb[HH*TE + lane] = 0.f; }

    for (int tile = t0; tile < ntiles; tile += PART*4) {
        if (lane < TE) {
            int idx = tile*TE + lane;
            float d = (idx < cnt) ? g_dist[idx] : 1e9f;
            float x0 = d * (1.0f/1.5f);
            float x1 = x0 - 1.0f;
            float x2 = x0 - 2.0f;
            float c0 = cosf(PI_2*x0), c1 = cosf(PI_2*x1), c2 = cosf(PI_2*x2);
            sb[lane]     = (fabsf(x0) < 1.f) ? c0*c0 : 0.f;
            sb[4 + lane] = (fabsf(x1) < 1.f) ? c1*c1 : 0.f;
            sb[8 + lane] = (fabsf(x2) < 1.f) ? c2*c2 : 0.f;
        }
        __syncwarp();
        float s0[TE], s1[TE], s2[TE];
        #pragma unroll
        for (int e = 0; e < TE; e++) {
            s0[e] = sb[e]; s1[e] = sb[4 + e]; s2[e] = sb[8 + e];
        }

        // layer 1: basis(3) -> 150
        #pragma unroll
        for (int q = 0; q < 5; q++) {
            int u = q*32 + lane;
            if (u < HH) {
                float wa = w1[u]        * INV_SQRT3;
                float wb = w1[HH + u]   * INV_SQRT3;
                float wc = w1[2*HH + u] * INV_SQRT3;
                float4 o;
                o.x = sp_act(fmaf(s0[0], wa, fmaf(s1[0], wb, s2[0]*wc)));
                o.y = sp_act(fmaf(s0[1], wa, fmaf(s1[1], wb, s2[1]*wc)));
                o.z = sp_act(fmaf(s0[2], wa, fmaf(s1[2], wb, s2[2]*wc)));
                o.w = sp_act(fmaf(s0[3], wa, fmaf(s1[3], wb, s2[3]*wc)));
                *reinterpret_cast<float4*>(ha + u*TE) = o;
            }
        }
        __syncwarp();
        hidden4(ha, hb, Wh2, lane);
        __syncwarp();
        hidden4(hb, ha, Wh3, lane);
        __syncwarp();

        if (layer == 0)      out4<32>(ha, g_Wo0, g_K0 + tile*TE*32, lane);
        else if (layer == 1) out4<64>(ha, g_Wo1, g_K1 + tile*TE*64, lane);
        else                 out4<64>(ha, g_Wo2, g_K2 + tile*TE*64, lane);
        __syncwarp();
    }
}

// ---------------- scatter (layers 0,1): out[b,i] += K(e) @ f[b,j] ----------
template<int LAYER>
__global__ void scatter_kernel() {
    constexpr int DIN  = (LAYER == 0) ? 4 : 8;
    constexpr int DOUT = 8;
    const float* __restrict__ K   = (LAYER == 0) ? g_K0 : g_K1;
    const float* __restrict__ fin = (LAYER == 0) ? g_f0 : g_f1;
    float*       __restrict__ fout= (LAYER == 0) ? g_f1 : g_f2;

    const int cnt = g_edge_count;
    const int total = cnt * DOUT;
    const float scale = rsqrtf(150.0f * (float)DIN);
    for (int t = blockIdx.x*blockDim.x + threadIdx.x; t < total;
         t += gridDim.x*blockDim.x) {
        int e = t / DOUT, a = t % DOUT;
        int p = g_packed[e];
        int b = p >> 20, i = (p >> 10) & 1023, j = p & 1023;
        const float* krow = K + e*(DIN*DOUT) + a*DIN;
        const float* fj = fin + (b*Nn + j)*DIN;
        const float* fi = fin + (b*Nn + i)*DIN;
        float s1 = 0.f, s2 = 0.f;
        #pragma unroll
        for (int ji = 0; ji < DIN; ji++) {
            float w = krow[ji];
            s1 = fmaf(w, fj[ji], s1);
            s2 = fmaf(w, fi[ji], s2);
        }
        atomicAdd(&fout[(b*Nn + i)*DOUT + a], s1 * scale);
        if (i != j) atomicAdd(&fout[(b*Nn + j)*DOUT + a], s2 * scale);
    }
}

// ---------------- scatter layer 2 + fused epilogue (last-block-done) -------
__global__ void scatter2_final_kernel(const float* __restrict__ lin_w,
                                      const float* __restrict__ lin_b,
                                      const float* __restrict__ bn_g,
                                      const float* __restrict__ bn_b,
                                      float* __restrict__ out) {
    constexpr int DIN = 8, DOUT = 8;
    const int cnt = g_edge_count;
    const int total = cnt * DOUT;
    const float scale = rsqrtf(150.0f * 8.0f);
    for (int t = blockIdx.x*blockDim.x + threadIdx.x; t < total;
         t += gridDim.x*blockDim.x) {
        int e = t / DOUT, a = t % DOUT;
        int p = g_packed[e];
        int b = p >> 20, i = (p >> 10) & 1023, j = p & 1023;
        const float* krow = g_K2 + e*(DIN*DOUT) + a*DIN;
        const float* fj = g_f2 + (b*Nn + j)*DIN;
        const float* fi = g_f2 + (b*Nn + i)*DIN;
        float s1 = 0.f, s2 = 0.f;
        #pragma unroll
        for (int ji = 0; ji < DIN; ji++) {
            float w = krow[ji];
            s1 = fmaf(w, fj[ji], s1);
            s2 = fmaf(w, fi[ji], s2);
        }
        atomicAdd(&g_f3[(b*Nn + i)*DOUT + a], s1 * scale);
        if (i != j) atomicAdd(&g_f3[(b*Nn + j)*DOUT + a], s2 * scale);
    }

    // last-block-done: final epilogue runs in the last block to arrive
    __threadfence();
    __shared__ int is_last;
    if (threadIdx.x == 0) {
        int ticket = atomicAdd(&g_done, 1);
        is_last = (ticket == (int)gridDim.x - 1);
    }
    __syncthreads();
    if (!is_last) return;

    __shared__ float pooled[2][24];
    __shared__ float yv[2][24];
    int t = threadIdx.x;
    if (t < 48) {
        int b = t / 24, c = t % 24;
        const float* src; int cc;
        if      (c < 8)  { src = g_f1; cc = c;      }
        else if (c < 16) { src = g_f2; cc = c - 8;  }
        else             { src = g_f3; cc = c - 16; }
        float s = 0.f;
        for (int n = 0; n < Nn; n++) {
            float v = src[(b*Nn + n)*8 + cc];
            s = fmaf(v, v, s);
        }
        pooled[b][c] = sqrtf(s + 1e-12f);
    }
    __syncthreads();
    if (t < 48) {
        int b = t / 24, o = t % 24;
        float s = lin_b[o];
        for (int c = 0; c < 24; c++) s = fmaf(pooled[b][c], lin_w[o*24 + c], s);
        yv[b][o] = s;
    }
    __syncthreads();
    if (t < 24) {
        float y0 = yv[0][t], y1 = yv[1][t];
        float m   = 0.5f * (y0 + y1);
        float d0  = y0 - m, d1 = y1 - m;
        float var = 0.5f * (d0*d0 + d1*d1);
        float inv = 1.0f / sqrtf(var + 1e-5f);
        #pragma unroll
        for (int b = 0; b < 2; b++) {
            float v = (yv[b][t] - m) * inv * bn_g[t] + bn_b[t];
            out[b*24 + t] = (v > 0.f) ? v : 0.2f * v;
        }
    }
}

// ---------------- launch: 6 kernels total ----------------------------------
extern "C" void kernel_launch(void* const* d_in, const int* in_sizes, int n_in,
                              void* d_out, int out_size) {
    const float* xyz   = (const float*)d_in[0];
    const int*   Z     = (const int*)  d_in[1];
    const float* emb   = (const float*)d_in[2];
    const float* c0w1  = (const float*)d_in[3];
    const float* c0w2  = (const float*)d_in[4];
    const float* c0w3  = (const float*)d_in[5];
    const float* c0wo  = (const float*)d_in[6];
    const float* c1w1  = (const float*)d_in[7];
    const float* c1w2  = (const float*)d_in[8];
    const float* c1w3  = (const float*)d_in[9];
    const float* c1wo  = (const float*)d_in[10];
    const float* c2w1  = (const float*)d_in[11];
    const float* c2w2  = (const float*)d_in[12];
    const float* c2w3  = (const float*)d_in[13];
    const float* c2wo  = (const float*)d_in[14];
    const float* lin_w = (const float*)d_in[15];
    const float* lin_b = (const float*)d_in[16];
    const float* bn_g  = (const float*)d_in[17];
    const float* bn_b  = (const float*)d_in[18];
    float* out = (float*)d_out;

    reset_kernel<<<1, 32>>>();
    prep_kernel<<<1324, 256>>>(Z, emb, xyz,
                               c0w2, c0w3, c1w2, c1w3, c2w2, c2w3,
                               c0wo, c1wo, c2wo);
    radial_kernel<<<3*PART, 128>>>(c0w1, c1w1, c2w1);
    scatter_kernel<0><<<296, 256>>>();
    scatter_kernel<1><<<296, 256>>>();
    scatter2_final_kernel<<<296, 256>>>(lin_w, lin_b, bn_g, bn_b, out);
}